// round 14
// baseline (speedup 1.0000x reference)
#include <cuda_runtime.h>
#include <cuda_bf16.h>
#include <math.h>
#include <stdint.h>

#define BB    2
#define TT    5
#define CC    64
#define HH    128
#define WW    128
#define H2    64
#define W2    64
#define GG    8
#define KK9   9
#define OFFC  144
#define TCEN  2
#define NJ    8
#define HW    (HH*WW)
#define HW2   (H2*W2)

typedef unsigned short ushort_t;

// ---- scratch (device globals; no allocations allowed) ----
__device__ float    g_off2[NJ*OFFC*HW2];
__device__ float    g_off2us[NJ*OFFC*HW];
__device__ float    g_off1[NJ*OFFC*HW];
__device__ float    g_xt[BB*TT*HW*CC];      // x transposed: [bt][pix][c]
// packed (bf16hi<<16 | bf16lo) inputs for conv A staging
__device__ uint32_t g_x2p[BB*TT*CC*HW2];
__device__ uint32_t g_xcp[BB*CC*HW];
__device__ uint32_t g_z1p[NJ*CC*HW];
// conv weights pre-split hi/lo bf16
__device__ ushort_t g_w5pH[OFFC*128*25], g_w5pL[OFFC*128*25];
__device__ ushort_t g_w3pH[OFFC*128*9],  g_w3pL[OFFC*128*9];
// deform weights packed [pair][o][c]
__device__ uint32_t g_wd1p[72*64*8];
__device__ uint32_t g_wdfp[72*64*8];
__device__ int2     g_tab5[128*25];
__device__ int2     g_tab3[128*9];

__device__ __forceinline__ int job_frame(int fi) { return fi + (fi >= TCEN ? 1 : 0); }

__device__ __forceinline__ uint32_t packhl(float v) {
    __nv_bfloat16 h = __float2bfloat16(v);
    __nv_bfloat16 l = __float2bfloat16(v - __bfloat162float(h));
    return ((uint32_t)__bfloat16_as_ushort(h) << 16) | (uint32_t)__bfloat16_as_ushort(l);
}
__device__ __forceinline__ uint32_t smem_u32(const void* p) {
    uint32_t a;
    asm("{ .reg .u64 t; cvta.to.shared.u64 t, %1; cvt.u32.u64 %0, t; }" : "=r"(a) : "l"(p));
    return a;
}
__device__ __forceinline__ void ldmx4(uint32_t* r, uint32_t a) {
    asm volatile("ldmatrix.sync.aligned.m8n8.x4.shared.b16 {%0,%1,%2,%3}, [%4];"
        : "=r"(r[0]), "=r"(r[1]), "=r"(r[2]), "=r"(r[3]) : "r"(a));
}
__device__ __forceinline__ void mmabf(float* d, const uint32_t* a, const uint32_t* b) {
    asm volatile("mma.sync.aligned.m16n8k16.row.col.f32.bf16.bf16.f32 "
        "{%0,%1,%2,%3}, {%4,%5,%6,%7}, {%8,%9}, {%0,%1,%2,%3};"
        : "+f"(d[0]), "+f"(d[1]), "+f"(d[2]), "+f"(d[3])
        : "r"(a[0]), "r"(a[1]), "r"(a[2]), "r"(a[3]), "r"(b[0]), "r"(b[1]));
}

// ===========================================================================
// 1) 2x2 average pool + hi/lo pack
// ===========================================================================
__global__ void k_downsample(const float* __restrict__ x) {
    int idx = blockIdx.x * blockDim.x + threadIdx.x;
    if (idx >= BB*TT*CC*HW2) return;
    int xx = idx & 63;
    int yy = (idx >> 6) & 63;
    int c  = (idx >> 12) & 63;
    int bt = idx >> 18;
    const float* s = x + ((size_t)bt*CC + c)*HW + (yy*2)*WW + xx*2;
    g_x2p[idx] = packhl(0.25f * (s[0] + s[1] + s[WW] + s[WW+1]));
}

// ===========================================================================
// 2) center frame: passthrough + packed copy
// ===========================================================================
__global__ void k_center(const float* __restrict__ x, float* __restrict__ out) {
    int idx = blockIdx.x * blockDim.x + threadIdx.x;
    if (idx >= BB*CC*HW) return;
    int b    = idx >> 20;
    int rest = idx & ((1 << 20) - 1);
    size_t off = ((size_t)(b*TT + TCEN) << 20) + rest;
    float v = x[off];
    out[off] = v;
    g_xcp[idx] = packhl(v);
}

// ===========================================================================
// 2b) transpose x -> [bt][pix][c] for vectorized deform gathers
// ===========================================================================
__global__ void k_xpose(const float* __restrict__ x) {
    __shared__ float s[64][65];
    int bt = blockIdx.y;
    int p0 = blockIdx.x * 64;
    #pragma unroll
    for (int i = 0; i < 16; i++) {
        int idx = threadIdx.x + i*256;
        int c = idx >> 6, p = idx & 63;
        s[p][c] = x[((size_t)bt*CC + c)*HW + p0 + p];
    }
    __syncthreads();
    #pragma unroll
    for (int i = 0; i < 16; i++) {
        int idx = threadIdx.x + i*256;
        int p = idx >> 6, c = idx & 63;
        g_xt[((size_t)bt*HW + p0 + p)*64 + c] = s[p][c];
    }
}

// ===========================================================================
// 3) deform weight pack: [pair=g*9+k][o][c]
// ===========================================================================
__global__ void k_wdeform(const float* __restrict__ w1, const float* __restrict__ wf) {
    int idx = blockIdx.x * blockDim.x + threadIdx.x;
    if (idx >= 72*64*8) return;
    int c = idx & 7;
    int o = (idx >> 3) & 63;
    int p = idx >> 9;
    int g = p / 9, k = p - g*9;
    int src = (o*CC + g*8 + c)*KK9 + k;
    g_wd1p[idx] = packhl(w1[src]);
    g_wdfp[idx] = packhl(wf[src]);
}

// ===========================================================================
// 3b) conv weight split pack + im2col tap tables
// ===========================================================================
__global__ void k_pack2(const float* __restrict__ src,
                        ushort_t* __restrict__ dh, ushort_t* __restrict__ dl, int n) {
    int i = blockIdx.x * blockDim.x + threadIdx.x;
    if (i >= n) return;
    float v = src[i];
    __nv_bfloat16 h = __float2bfloat16(v);
    __nv_bfloat16 l = __float2bfloat16(v - __bfloat162float(h));
    dh[i] = __bfloat16_as_ushort(h);
    dl[i] = __bfloat16_as_ushort(l);
}
__global__ void k_tab() {
    int k = blockIdx.x * blockDim.x + threadIdx.x;
    if (k < 128*25) {
        int ci = k / 25, t = k % 25, ky = t / 5, kx = t % 5;
        g_tab5[k] = make_int2((ci & 63)*HW + (ky - 2)*WW + (kx - 2),
                              (ci >= 64 ? 1 : 0) | (ky << 8) | (kx << 16));
    }
    if (k < 128*9) {
        int ci = k / 9, t = k % 9, ky = t / 3, kx = t % 3;
        g_tab3[k] = make_int2((ci & 63)*HW2 + (ky - 1)*W2 + (kx - 1),
                              (ci >= 64 ? 1 : 0) | (ky << 8) | (kx << 16));
    }
}

// ===========================================================================
// 4) conv via mma.sync, producer/consumer pipeline.
//    512 thr: warps 0-7 compute M128xN144, warps 8-15 stage next chunk into
//    double-buffered dynamic smem. bf16 hi/lo 3-pass.
// ===========================================================================
#define SA 40
template<bool IS5>
__global__ __launch_bounds__(512) void k_convMMA(
    const uint32_t* __restrict__ pZall, const uint32_t* __restrict__ pCall,
    const ushort_t* __restrict__ wHg, const ushort_t* __restrict__ wLg,
    const float* __restrict__ bias)
{
    constexpr int KTAP = IS5 ? 25 : 9;
    constexpr int R    = IS5 ? 2 : 1;
    constexpr int KTOT = 128 * KTAP;
    constexpr int NCH  = KTOT / 32;
    constexpr int Wimg = IS5 ? 128 : 64;
    constexpr int Himg = Wimg;
    constexpr int LGW  = IS5 ? 7 : 6;
    constexpr int ABUF = 128*SA;            // ushorts
    constexpr int BBUF = 144*SA;
    constexpr int SBUF = 2*ABUF + 2*BBUF;   // per-buffer ushorts

    extern __shared__ __align__(16) ushort_t sm[];

    int tid = threadIdx.x, lane = tid & 31;
    int job = blockIdx.y, b = job >> 2, fi = job & 3;
    int frame = job_frame(fi);
    int tileBase = blockIdx.x * 128;

    const uint32_t *pZ, *pC;
    if (IS5) { pZ = pZall + (size_t)job*CC*HW;
               pC = pCall + (size_t)b*CC*HW; }
    else     { pZ = pZall + (size_t)(b*TT + frame)*CC*HW2;
               pC = pCall + (size_t)(b*TT + TCEN )*CC*HW2; }
    const int2* tab = IS5 ? g_tab5 : g_tab3;

    uint32_t smb = smem_u32(sm);
    bool isProd = tid >= 256;

    // ---- consumer state ----
    int w = tid >> 5, wm = w & 3, wn = w >> 2;
    float acc[2][9][4];
    #pragma unroll
    for (int mt = 0; mt < 2; mt++)
        #pragma unroll
        for (int j = 0; j < 9; j++)
            #pragma unroll
            for (int q = 0; q < 4; q++) acc[mt][j][q] = 0.f;
    int ar = (lane & 7) + ((lane >> 3) & 1) * 8;
    int ac = ((lane >> 4) & 1) * 8;
    uint32_t aOff[2];
    #pragma unroll
    for (int mt = 0; mt < 2; mt++)
        aOff[mt] = (uint32_t)(((wm*32 + mt*16 + ar)*SA + ac) * 2);
    int lane2 = lane & 15;
    uint32_t bCom = (uint32_t)(((lane2 & 7)*SA + ((lane2 >> 3) & 1) * 8) * 2);
    uint32_t bSelExtra = (lane < 16) ? 0u : (uint32_t)(BBUF * 2);  // BsH vs BsL

    // ---- producer state ----
    int ptid = tid - 256;
    int pw = ptid >> 5;    // 0..7 (valid when isProd)

    // ================= stage chunk 0 =================
    if (isProd) {
        int k0 = 0;
        ushort_t* AsH = sm;               ushort_t* AsL = sm + ABUF;
        ushort_t* BsH = sm + 2*ABUF;      ushort_t* BsL = BsH + BBUF;
        int kk0 = pw * 4;
        int2 e0 = tab[k0+kk0], e1 = tab[k0+kk0+1], e2 = tab[k0+kk0+2], e3 = tab[k0+kk0+3];
        int pl = ptid & 31;
        #pragma unroll
        for (int pp = 0; pp < 4; pp++) {
            int m = pl + pp * 32;
            int pixel = tileBase + m;
            int py = pixel >> LGW, px = pixel & (Wimg - 1);
            uint32_t u[4];
            int2 ee[4] = {e0, e1, e2, e3};
            #pragma unroll
            for (int q = 0; q < 4; q++) {
                int ky = (ee[q].y >> 8) & 0xFF, kx = (ee[q].y >> 16) & 0xFF;
                int yy = py + ky - R, xx = px + kx - R;
                u[q] = 0u;
                if ((unsigned)yy < (unsigned)Himg && (unsigned)xx < (unsigned)Wimg)
                    u[q] = __ldg(((ee[q].y & 1) ? pC : pZ) + ee[q].x + pixel);
            }
            uint32_t* dH = (uint32_t*)(AsH + m*SA + kk0);
            uint32_t* dL = (uint32_t*)(AsL + m*SA + kk0);
            dH[0] = (u[0] >> 16) | (u[1] & 0xFFFF0000u);
            dH[1] = (u[2] >> 16) | (u[3] & 0xFFFF0000u);
            dL[0] = (u[0] & 0xFFFFu) | (u[1] << 16);
            dL[1] = (u[2] & 0xFFFFu) | (u[3] << 16);
        }
        #pragma unroll
        for (int i = 0; i < 9; i++) {
            int l = ptid + i * 256;
            int n = l >> 4, kp = l & 15;
            uint32_t uh = ((const uint32_t*)(wHg + (size_t)n*KTOT + k0))[kp];
            uint32_t ul = ((const uint32_t*)(wLg + (size_t)n*KTOT + k0))[kp];
            *(uint32_t*)(BsH + n*SA + 2*kp) = uh;
            *(uint32_t*)(BsL + n*SA + 2*kp) = ul;
        }
    }
    __syncthreads();

    // ================= main pipeline =================
    for (int c = 0; c < NCH; c++) {
        if (!isProd) {
            uint32_t base = smb + (uint32_t)(c & 1) * (SBUF * 2);
            uint32_t aHb = base, aLb = base + ABUF*2;
            uint32_t bBase = base + 2*ABUF*2 + bSelExtra;   // per-lane BsH/BsL
            #pragma unroll
            for (int kh = 0; kh < 2; kh++) {
                uint32_t aH[2][4], aL[2][4];
                #pragma unroll
                for (int mt = 0; mt < 2; mt++) {
                    ldmx4(aH[mt], aHb + aOff[mt] + kh*32);
                    ldmx4(aL[mt], aLb + aOff[mt] + kh*32);
                }
                #pragma unroll
                for (int j = 0; j < 9; j++) {
                    uint32_t r[4];
                    ldmx4(r, bBase + (uint32_t)((wn*72 + j*8)*SA*2) + bCom + kh*32);
                    #pragma unroll
                    for (int mt = 0; mt < 2; mt++) {
                        mmabf(acc[mt][j], aH[mt], r);       // hh
                        mmabf(acc[mt][j], aH[mt], r + 2);   // hl
                        mmabf(acc[mt][j], aL[mt], r);       // lh
                    }
                }
            }
        } else if (c + 1 < NCH) {
            int k0 = (c + 1) * 32;
            int bsel = (c + 1) & 1;
            ushort_t* AsH = sm + bsel*SBUF;   ushort_t* AsL = AsH + ABUF;
            ushort_t* BsH = AsL + ABUF;       ushort_t* BsL = BsH + BBUF;
            int kk0 = pw * 4;
            int2 e0 = tab[k0+kk0], e1 = tab[k0+kk0+1], e2 = tab[k0+kk0+2], e3 = tab[k0+kk0+3];
            int pl = ptid & 31;
            #pragma unroll
            for (int pp = 0; pp < 4; pp++) {
                int m = pl + pp * 32;
                int pixel = tileBase + m;
                int py = pixel >> LGW, px = pixel & (Wimg - 1);
                uint32_t u[4];
                int2 ee[4] = {e0, e1, e2, e3};
                #pragma unroll
                for (int q = 0; q < 4; q++) {
                    int ky = (ee[q].y >> 8) & 0xFF, kx = (ee[q].y >> 16) & 0xFF;
                    int yy = py + ky - R, xx = px + kx - R;
                    u[q] = 0u;
                    if ((unsigned)yy < (unsigned)Himg && (unsigned)xx < (unsigned)Wimg)
                        u[q] = __ldg(((ee[q].y & 1) ? pC : pZ) + ee[q].x + pixel);
                }
                uint32_t* dH = (uint32_t*)(AsH + m*SA + kk0);
                uint32_t* dL = (uint32_t*)(AsL + m*SA + kk0);
                dH[0] = (u[0] >> 16) | (u[1] & 0xFFFF0000u);
                dH[1] = (u[2] >> 16) | (u[3] & 0xFFFF0000u);
                dL[0] = (u[0] & 0xFFFFu) | (u[1] << 16);
                dL[1] = (u[2] & 0xFFFFu) | (u[3] << 16);
            }
            #pragma unroll
            for (int i = 0; i < 9; i++) {
                int l = ptid + i * 256;
                int n = l >> 4, kp = l & 15;
                uint32_t uh = ((const uint32_t*)(wHg + (size_t)n*KTOT + k0))[kp];
                uint32_t ul = ((const uint32_t*)(wLg + (size_t)n*KTOT + k0))[kp];
                *(uint32_t*)(BsH + n*SA + 2*kp) = uh;
                *(uint32_t*)(BsL + n*SA + 2*kp) = ul;
            }
        }
        __syncthreads();
    }

    // ================= epilogue (consumers) =================
    if (!isProd) {
        int r0 = lane >> 2, cp = (lane & 3) * 2;
        #pragma unroll
        for (int mt = 0; mt < 2; mt++) {
            #pragma unroll
            for (int j = 0; j < 9; j++) {
                int col = wn*72 + j*8 + cp;
                int rowA = tileBase + wm*32 + mt*16 + r0;
                float b0 = __ldg(bias + col), b1 = __ldg(bias + col + 1);
                #pragma unroll
                for (int h = 0; h < 2; h++) {
                    int pix = rowA + h*8;
                    float v0 = acc[mt][j][2*h    ] + b0;
                    float v1 = acc[mt][j][2*h + 1] + b1;
                    if (IS5) {
                        size_t i0 = (size_t)job*OFFC*HW + (size_t)col*HW + pix;
                        size_t i1 = i0 + HW;
                        g_off1[i0] = v0 + g_off2us[i0];
                        g_off1[i1] = v1 + g_off2us[i1];
                    } else {
                        size_t i0 = (size_t)job*OFFC*HW2 + (size_t)col*HW2 + pix;
                        g_off2[i0      ] = v0;
                        g_off2[i0 + HW2] = v1;
                    }
                }
            }
        }
    }
}

// ===========================================================================
// 5) 2x bilinear upsample * 2.0, fixed weights {0.25,0.75}
// ===========================================================================
__global__ void k_upsample2() {
    int idx = blockIdx.x * blockDim.x + threadIdx.x;
    if (idx >= NJ*OFFC*HW2) return;
    int j = idx & 63;
    int i = (idx >> 6) & 63;
    int plane = idx >> 12;
    const float* p = g_off2 + (size_t)plane*HW2;

    int im1 = max(i-1, 0), ip1 = min(i+1, H2-1);
    int jm1 = max(j-1, 0), jp1 = min(j+1, W2-1);
    float vtl = p[im1*W2+jm1], vtc = p[im1*W2+j], vtr = p[im1*W2+jp1];
    float vml = p[i  *W2+jm1], vmc = p[i  *W2+j], vmr = p[i  *W2+jp1];
    float vbl = p[ip1*W2+jm1], vbc = p[ip1*W2+j], vbr = p[ip1*W2+jp1];

    float h0t = 0.25f*vtl + 0.75f*vtc, h1t = 0.75f*vtc + 0.25f*vtr;
    float h0m = 0.25f*vml + 0.75f*vmc, h1m = 0.75f*vmc + 0.25f*vmr;
    float h0b = 0.25f*vbl + 0.75f*vbc, h1b = 0.75f*vbc + 0.25f*vbr;

    float* d = g_off2us + (size_t)plane*HW;
    float2 r0 = make_float2(2.f*(0.25f*h0t + 0.75f*h0m), 2.f*(0.25f*h1t + 0.75f*h1m));
    float2 r1 = make_float2(2.f*(0.75f*h0m + 0.25f*h0b), 2.f*(0.75f*h1m + 0.25f*h1b));
    *(float2*)(d + (2*i  )*WW + 2*j) = r0;
    *(float2*)(d + (2*i+1)*WW + 2*j) = r1;
}

// ===========================================================================
// 6) deformable conv via mma.sync, vectorized gathers from g_xt.
// ===========================================================================
#define DSA 24
__global__ __launch_bounds__(256) void k_deformMMA(
    float* __restrict__ out, const uint32_t* __restrict__ wpk, int final_mode)
{
    __shared__ __align__(16) char smem[64*132*4];
    ushort_t* AsH = (ushort_t*)smem;
    ushort_t* AsL = AsH + 128*DSA;
    ushort_t* BsH = AsL + 128*DSA;
    ushort_t* BsL = BsH + 64*DSA;
    float* sOut = (float*)smem;

    int tid = threadIdx.x, lane = tid & 31, w = tid >> 5;
    int wm = w & 3, wn = w >> 2;
    int job = blockIdx.y, b = job >> 2, fi = job & 3;
    int frame = job_frame(fi);
    int tileBase = blockIdx.x * 128;

    const float* xt   = g_xt + (size_t)(b*TT + frame)*HW*64;
    const float* offs = (final_mode ? g_off1 : g_off2us) + (size_t)job*OFFC*HW;

    int m   = tid & 127;
    int sel = tid >> 7;
    int pixel = tileBase + m;
    int py = pixel >> 7, px = pixel & 127;

    int bo = tid & 63, bhalf = tid >> 6;
    int bpr = bhalf >> 1, bcq = (bhalf & 1)*4;

    float acc[2][4][4];
    #pragma unroll
    for (int mt = 0; mt < 2; mt++)
        #pragma unroll
        for (int j = 0; j < 4; j++)
            #pragma unroll
            for (int q = 0; q < 4; q++) acc[mt][j][q] = 0.f;

    uint32_t aHb = smem_u32(AsH), aLb = smem_u32(AsL);
    uint32_t bHb = smem_u32(BsH);
    int ar = (lane & 7) + ((lane >> 3) & 1) * 8;
    int ac = ((lane >> 4) & 1) * 8;
    uint32_t aOff[2];
    #pragma unroll
    for (int mt = 0; mt < 2; mt++)
        aOff[mt] = (uint32_t)(((wm*32 + mt*16 + ar)*DSA + ac) * 2);
    int lane2 = lane & 15;
    uint32_t bCom = (uint32_t)(((lane2 & 7)*DSA + ((lane2 >> 3) & 1) * 8) * 2);
    uint32_t bBase = bHb + ((lane < 16) ? 0u : (uint32_t)(64*DSA*2)) + bCom;

    #pragma unroll 1
    for (int ch = 0; ch < 36; ch++) {
        int p0 = ch * 2;
        __syncthreads();

        // ---- stage A: sample 8 channels for pair (p0+sel) at my pixel
        {
            int p = p0 + sel;
            int g = p / 9, k = p - g*9;
            float dy = __ldg(offs + (size_t)(2*p)*HW + pixel);
            float dx = __ldg(offs + (size_t)(2*p+1)*HW + pixel);
            float sy = dy + (float)(py + k/3 - 1);
            float sx = dx + (float)(px + (k - (k/3)*3) - 1);
            float fy0 = floorf(sy), fx0 = floorf(sx);
            float wy = sy - fy0, wx = sx - fx0;
            int y0 = (int)fy0, xx0 = (int)fx0;
            int y1 = y0 + 1,   xx1 = xx0 + 1;
            bool vy0 = (unsigned)y0  < HH, vy1 = (unsigned)y1  < HH;
            bool vx0 = (unsigned)xx0 < WW, vx1 = (unsigned)xx1 < WW;
            int y0c = min(max(y0, 0), HH-1), y1c = min(max(y1, 0), HH-1);
            int x0c = min(max(xx0,0), WW-1), x1c = min(max(xx1,0), WW-1);
            float w00 = (vy0 && vx0) ? (1.f-wy)*(1.f-wx) : 0.f;
            float w01 = (vy0 && vx1) ? (1.f-wy)*wx       : 0.f;
            float w10 = (vy1 && vx0) ? wy*(1.f-wx)       : 0.f;
            float w11 = (vy1 && vx1) ? wy*wx             : 0.f;

            const float* base = xt + (size_t)g*8;
            const float4* t00 = (const float4*)(base + (size_t)(y0c*WW + x0c)*64);
            const float4* t01 = (const float4*)(base + (size_t)(y0c*WW + x1c)*64);
            const float4* t10 = (const float4*)(base + (size_t)(y1c*WW + x0c)*64);
            const float4* t11 = (const float4*)(base + (size_t)(y1c*WW + x1c)*64);
            float4 a00 = __ldg(t00), b00 = __ldg(t00+1);
            float4 a01 = __ldg(t01), b01 = __ldg(t01+1);
            float4 a10 = __ldg(t10), b10 = __ldg(t10+1);
            float4 a11 = __ldg(t11), b11 = __ldg(t11+1);
            float v[8];
            v[0] = w00*a00.x + w01*a01.x + w10*a10.x + w11*a11.x;
            v[1] = w00*a00.y + w01*a01.y + w10*a10.y + w11*a11.y;
            v[2] = w00*a00.z + w01*a01.z + w10*a10.z + w11*a11.z;
            v[3] = w00*a00.w + w01*a01.w + w10*a10.w + w11*a11.w;
            v[4] = w00*b00.x + w01*b01.x + w10*b10.x + w11*b11.x;
            v[5] = w00*b00.y + w01*b01.y + w10*b10.y + w11*b11.y;
            v[6] = w00*b00.z + w01*b01.z + w10*b10.z + w11*b11.z;
            v[7] = w00*b00.w + w01*b01.w + w10*b10.w + w11*b11.w;

            uint32_t hiw[4], low[4];
            #pragma unroll
            for (int c2 = 0; c2 < 4; c2++) {
                uint32_t u0 = packhl(v[2*c2]), u1 = packhl(v[2*c2+1]);
                hiw[c2] = (u0 >> 16)     | (u1 & 0xFFFF0000u);
                low[c2] = (u0 & 0xFFFFu) | (u1 << 16);
            }
            *(uint4*)(AsH + m*DSA + sel*8) = make_uint4(hiw[0], hiw[1], hiw[2], hiw[3]);
            *(uint4*)(AsL + m*DSA + sel*8) = make_uint4(low[0], low[1], low[2], low[3]);
        }
        // ---- stage B
        {
            const uint32_t* src = wpk + ((size_t)(p0 + bpr)*64 + bo)*8 + bcq;
            uint32_t u0 = __ldg(src), u1 = __ldg(src+1), u2 = __ldg(src+2), u3 = __ldg(src+3);
            uint2 hv, lv;
            hv.x = (u0 >> 16) | (u1 & 0xFFFF0000u);
            hv.y = (u2 >> 16) | (u3 & 0xFFFF0000u);
            lv.x = (u0 & 0xFFFFu) | (u1 << 16);
            lv.y = (u2 & 0xFFFFu) | (u3 << 16);
            *(uint2*)(BsH + bo*DSA + bpr*8 + bcq) = hv;
            *(uint2*)(BsL + bo*DSA + bpr*8 + bcq) = lv;
        }
        __syncthreads();

        // ---- compute
        uint32_t aH[2][4], aL[2][4];
        #pragma unroll
        for (int mt = 0; mt < 2; mt++) {
            ldmx4(aH[mt], aHb + aOff[mt]);
            ldmx4(aL[mt], aLb + aOff[mt]);
        }
        #pragma unroll
        for (int j = 0; j < 4; j++) {
            uint32_t r[4];
            ldmx4(r, bBase + (uint32_t)((wn*32 + j*8)*DSA*2));
            #pragma unroll
            for (int mt = 0; mt < 2; mt++) {
                mmabf(acc[mt][j], aH[mt], r);
                mmabf(acc[mt][j], aH[mt], r + 2);
                mmabf(acc[mt][j], aL[mt], r);
            }
        }
    }

    // ---- epilogue
    __syncthreads();
    {
        int r0 = lane >> 2, cp = (lane & 3) * 2;
        #pragma unroll
        for (int mt = 0; mt < 2; mt++) {
            #pragma unroll
            for (int j = 0; j < 4; j++) {
                int col = wn*32 + j*8 + cp;
                int row = wm*32 + mt*16 + r0;
                sOut[ col   *132 + row    ] = acc[mt][j][0];
                sOut[(col+1)*132 + row    ] = acc[mt][j][1];
                sOut[ col   *132 + row + 8] = acc[mt][j][2];
                sOut[(col+1)*132 + row + 8] = acc[mt][j][3];
            }
        }
    }
    __syncthreads();

    if (final_mode) {
        float* ob = out + ((size_t)(b*TT + frame)*CC)*HW + tileBase;
        #pragma unroll
        for (int it = 0; it < 32; it++) {
            int idx = it*256 + tid;
            int o = idx >> 7, pxl = idx & 127;
            ob[(size_t)o*HW + pxl] = sOut[o*132 + pxl];
        }
    } else {
        uint32_t* ob = g_z1p + (size_t)job*CC*HW + tileBase;
        #pragma unroll
        for (int it = 0; it < 32; it++) {
            int idx = it*256 + tid;
            int o = idx >> 7, pxl = idx & 127;
            ob[(size_t)o*HW + pxl] = packhl(sOut[o*132 + pxl]);
        }
    }
}

// ===========================================================================
extern "C" void kernel_launch(void* const* d_in, const int* in_sizes, int n_in,
                              void* d_out, int out_size) {
    const float* x        = (const float*)d_in[0];
    const float* w_off1   = (const float*)d_in[1];
    const float* b_off1   = (const float*)d_in[2];
    const float* w_off2   = (const float*)d_in[3];
    const float* b_off2   = (const float*)d_in[4];
    const float* w_align1 = (const float*)d_in[5];
    const float* w_alignf = (const float*)d_in[6];
    float* out = (float*)d_out;

    ushort_t *w5H = nullptr, *w5L = nullptr, *w3H = nullptr, *w3L = nullptr;
    uint32_t *z1p = nullptr, *x2p = nullptr, *xcp = nullptr, *wd1 = nullptr, *wdf = nullptr;
    cudaGetSymbolAddress((void**)&w5H, g_w5pH);
    cudaGetSymbolAddress((void**)&w5L, g_w5pL);
    cudaGetSymbolAddress((void**)&w3H, g_w3pH);
    cudaGetSymbolAddress((void**)&w3L, g_w3pL);
    cudaGetSymbolAddress((void**)&z1p, g_z1p);
    cudaGetSymbolAddress((void**)&x2p, g_x2p);
    cudaGetSymbolAddress((void**)&xcp, g_xcp);
    cudaGetSymbolAddress((void**)&wd1, g_wd1p);
    cudaGetSymbolAddress((void**)&wdf, g_wdfp);

    const int convSmem = 2 * (2*128*SA + 2*144*SA) * 2;   // 87040 B
    cudaFuncSetAttribute(k_convMMA<false>, cudaFuncAttributeMaxDynamicSharedMemorySize, convSmem);
    cudaFuncSetAttribute(k_convMMA<true>,  cudaFuncAttributeMaxDynamicSharedMemorySize, convSmem);

    k_downsample<<<(BB*TT*CC*HW2 + 255)/256, 256>>>(x);
    k_center<<<(BB*CC*HW + 255)/256, 256>>>(x, out);
    k_xpose<<<dim3(HW/64, BB*TT), 256>>>(x);
    k_wdeform<<<(72*64*8 + 255)/256, 256>>>(w_align1, w_alignf);
    k_pack2<<<(OFFC*128*25 + 255)/256, 256>>>(w_off1, w5H, w5L, OFFC*128*25);
    k_pack2<<<(OFFC*128*9  + 255)/256, 256>>>(w_off2, w3H, w3L, OFFC*128*9);
    k_tab<<<(128*25 + 255)/256, 256>>>();

    k_convMMA<false><<<dim3(HW2/128, NJ), 512, convSmem>>>(x2p, x2p, w3H, w3L, b_off2);
    k_upsample2<<<(NJ*OFFC*HW2 + 255)/256, 256>>>();
    k_deformMMA<<<dim3(HW/128, NJ), 256>>>(out, wd1, 0);
    k_convMMA<true><<<dim3(HW/128, NJ), 512, convSmem>>>(z1p, xcp, w5H, w5L, b_off1);
    k_deformMMA<<<dim3(HW/128, NJ), 256>>>(out, wdf, 1);
}